// round 1
// baseline (speedup 1.0000x reference)
#include <cuda_runtime.h>
#include <math.h>
#include <stdint.h>

// Problem constants (fixed by reference setup_inputs)
#define CB 4
#define CL 2048
#define CD 256
#define CH 8
#define CDK 32
#define CF 1024

// Scratch (device globals: allocation-free per harness rules)
__device__ __align__(16) float g_m[CL * CDK];                     // 256 KB
__device__ __align__(16) float g_S[(size_t)CL * CL];              // 16 MB
__device__ __align__(16) float g_A[(size_t)CB * CL * CL];         // 64 MB
__device__ __align__(16) float g_T[(size_t)CB * CL * CD];         // 8 MB
__device__ __align__(16) float g_Hn[(size_t)CB * CL * CD];        // 8 MB
__device__ __align__(16) float g_H1[(size_t)CB * CL * CF];        // 32 MB
__device__ __align__(16) float g_Y[(size_t)CB * CL * CD];         // 8 MB

// ---------------------------------------------------------------------------
// m[l, d] = mean over (b, h) of x[b, l, h*32 + d]
// ---------------------------------------------------------------------------
__global__ void k_mean(const float* __restrict__ x) {
    int idx = blockIdx.x * blockDim.x + threadIdx.x;
    if (idx >= CL * CDK) return;
    int l = idx / CDK;
    int d = idx % CDK;
    float s = 0.f;
#pragma unroll
    for (int b = 0; b < CB; b++) {
#pragma unroll
        for (int h = 0; h < CH; h++) {
            s += x[((size_t)(b * CL) + l) * CD + h * CDK + d];
        }
    }
    g_m[idx] = s * (1.f / 32.f);
}

// ---------------------------------------------------------------------------
// S[i, j] = sin(clip(m_i . m_j, -pi, pi) * 0.5)^2
// ---------------------------------------------------------------------------
__global__ void k_scores() {
    __shared__ float mi[16][33];
    __shared__ float mj[16][33];
    int i0 = blockIdx.y * 16;
    int j0 = blockIdx.x * 16;
    int tx = threadIdx.x, ty = threadIdx.y;
    int t = ty * 16 + tx;
    for (int v = t; v < 16 * 32; v += 256) {
        int r = v >> 5, c = v & 31;
        mi[r][c] = g_m[(i0 + r) * CDK + c];
        mj[r][c] = g_m[(j0 + r) * CDK + c];
    }
    __syncthreads();
    float dot = 0.f;
#pragma unroll
    for (int k = 0; k < 32; k++) dot = fmaf(mi[ty][k], mj[tx][k], dot);
    const float PI = 3.14159265358979323846f;
    float ang = fminf(fmaxf(dot, -PI), PI);
    float s = sinf(ang * 0.5f);
    g_S[(size_t)(i0 + ty) * CL + (j0 + tx)] = s * s;
}

// ---------------------------------------------------------------------------
// Row softmax with key mask: A[b, i, :] = softmax_j( mask[b,j] ? S[i,j] : -1e9 )
// ---------------------------------------------------------------------------
__global__ void k_softmax(const int* __restrict__ mask) {
    __shared__ float sm[CL];
    __shared__ float red[8];
    int bi = blockIdx.x;
    int b = bi >> 11;           // /2048
    int i = bi & (CL - 1);
    int tid = threadIdx.x;      // 256 threads
    const float* Srow = g_S + (size_t)i * CL;
    const int* mrow = mask + b * CL;

    float mx = -1e30f;
    for (int j = tid; j < CL; j += 256) {
        float v = (mrow[j] == 0) ? -1e9f : Srow[j];
        sm[j] = v;
        mx = fmaxf(mx, v);
    }
    for (int o = 16; o > 0; o >>= 1) mx = fmaxf(mx, __shfl_xor_sync(0xffffffffu, mx, o));
    if ((tid & 31) == 0) red[tid >> 5] = mx;
    __syncthreads();
    if (tid < 32) {
        float r = (tid < 8) ? red[tid] : -1e30f;
        for (int o = 4; o > 0; o >>= 1) r = fmaxf(r, __shfl_xor_sync(0xffffffffu, r, o));
        if (tid == 0) red[0] = r;
    }
    __syncthreads();
    mx = red[0];
    __syncthreads();

    float sum = 0.f;
    for (int j = tid; j < CL; j += 256) {
        float e = expf(sm[j] - mx);
        sm[j] = e;
        sum += e;
    }
    for (int o = 16; o > 0; o >>= 1) sum += __shfl_xor_sync(0xffffffffu, sum, o);
    if ((tid & 31) == 0) red[tid >> 5] = sum;
    __syncthreads();
    if (tid < 32) {
        float r = (tid < 8) ? red[tid] : 0.f;
        for (int o = 4; o > 0; o >>= 1) r += __shfl_xor_sync(0xffffffffu, r, o);
        if (tid == 0) red[0] = r;
    }
    __syncthreads();
    float inv = 1.f / red[0];

    float* Arow = g_A + ((size_t)b * CL + i) * CL;
    for (int j = tid; j < CL; j += 256) Arow[j] = sm[j] * inv;
}

// ---------------------------------------------------------------------------
// Tiled fp32 GEMM: C = A(MxK,row) * B(KxN,row) [+bias][relu][+res]
// BM=128, BN=64, BK=16, TM=8, TN=4, 256 threads. Dims must divide tiles.
// OPT bits: 1 = bias, 2 = relu, 4 = residual
// ---------------------------------------------------------------------------
template <int OPT>
__global__ void __launch_bounds__(256) k_sgemm(
    const float* __restrict__ A, const float* __restrict__ B,
    const float* __restrict__ bias, const float* __restrict__ Rs,
    float* __restrict__ C, int M, int N, int K,
    size_t sA, size_t sB, size_t sR, size_t sC)
{
    constexpr int BM = 128, BN = 64, BK = 16, TM = 8, TN = 4;
    A += (size_t)blockIdx.z * sA;
    B += (size_t)blockIdx.z * sB;
    C += (size_t)blockIdx.z * sC;
    if (OPT & 4) Rs += (size_t)blockIdx.z * sR;

    __shared__ float As[BK][BM + 4];
    __shared__ float Bs[BK][BN];

    int tid = threadIdx.x;
    int tx = tid & 15;     // N direction, 16
    int ty = tid >> 4;     // M direction, 16
    int m0 = blockIdx.y * BM;
    int n0 = blockIdx.x * BN;

    float acc[TM][TN];
#pragma unroll
    for (int i = 0; i < TM; i++)
#pragma unroll
        for (int j = 0; j < TN; j++) acc[i][j] = 0.f;

    for (int k0 = 0; k0 < K; k0 += BK) {
        // Load A tile (BMxBK), store transposed into As[BK][BM]
#pragma unroll
        for (int u = 0; u < 2; u++) {
            int v = tid + u * 256;      // 0..511
            int r = v >> 2;             // 0..127
            int c4 = v & 3;             // 0..3
            float4 a = *(const float4*)&A[(size_t)(m0 + r) * K + k0 + c4 * 4];
            As[c4 * 4 + 0][r] = a.x;
            As[c4 * 4 + 1][r] = a.y;
            As[c4 * 4 + 2][r] = a.z;
            As[c4 * 4 + 3][r] = a.w;
        }
        // Load B tile (BKxBN)
        {
            int r = tid >> 4;           // 0..15
            int c4 = tid & 15;          // 0..15
            float4 bv = *(const float4*)&B[(size_t)(k0 + r) * N + n0 + c4 * 4];
            *(float4*)&Bs[r][c4 * 4] = bv;
        }
        __syncthreads();

#pragma unroll
        for (int kk = 0; kk < BK; kk++) {
            float4 a0 = *(const float4*)&As[kk][ty * TM];
            float4 a1 = *(const float4*)&As[kk][ty * TM + 4];
            float4 b0 = *(const float4*)&Bs[kk][tx * TN];
            float a[TM] = {a0.x, a0.y, a0.z, a0.w, a1.x, a1.y, a1.z, a1.w};
            float bb[TN] = {b0.x, b0.y, b0.z, b0.w};
#pragma unroll
            for (int i = 0; i < TM; i++)
#pragma unroll
                for (int j = 0; j < TN; j++)
                    acc[i][j] = fmaf(a[i], bb[j], acc[i][j]);
        }
        __syncthreads();
    }

    int col = n0 + tx * TN;
    float4 bb4 = make_float4(0.f, 0.f, 0.f, 0.f);
    if (OPT & 1) bb4 = *(const float4*)&bias[col];
#pragma unroll
    for (int i = 0; i < TM; i++) {
        int row = m0 + ty * TM + i;
        float4 c = make_float4(acc[i][0], acc[i][1], acc[i][2], acc[i][3]);
        if (OPT & 1) { c.x += bb4.x; c.y += bb4.y; c.z += bb4.z; c.w += bb4.w; }
        if (OPT & 2) {
            c.x = fmaxf(c.x, 0.f); c.y = fmaxf(c.y, 0.f);
            c.z = fmaxf(c.z, 0.f); c.w = fmaxf(c.w, 0.f);
        }
        if (OPT & 4) {
            float4 rr = *(const float4*)&Rs[(size_t)row * N + col];
            c.x += rr.x; c.y += rr.y; c.z += rr.z; c.w += rr.w;
        }
        *(float4*)&C[(size_t)row * N + col] = c;
    }
}

// ---------------------------------------------------------------------------
// LayerNorm over last dim D=256 (one block of 256 threads per row)
// ---------------------------------------------------------------------------
__global__ void k_ln(const float* __restrict__ in, const float* __restrict__ gw,
                     const float* __restrict__ bw, float* __restrict__ out) {
    __shared__ float red[8];
    int row = blockIdx.x;
    int tid = threadIdx.x;
    float v = in[(size_t)row * CD + tid];

    float s = v;
    for (int o = 16; o > 0; o >>= 1) s += __shfl_xor_sync(0xffffffffu, s, o);
    if ((tid & 31) == 0) red[tid >> 5] = s;
    __syncthreads();
    if (tid < 32) {
        float r = (tid < 8) ? red[tid] : 0.f;
        for (int o = 4; o > 0; o >>= 1) r += __shfl_xor_sync(0xffffffffu, r, o);
        if (tid == 0) red[0] = r;
    }
    __syncthreads();
    float mu = red[0] * (1.f / CD);
    __syncthreads();

    float t = v - mu;
    float s2 = t * t;
    for (int o = 16; o > 0; o >>= 1) s2 += __shfl_xor_sync(0xffffffffu, s2, o);
    if ((tid & 31) == 0) red[tid >> 5] = s2;
    __syncthreads();
    if (tid < 32) {
        float r = (tid < 8) ? red[tid] : 0.f;
        for (int o = 4; o > 0; o >>= 1) r += __shfl_xor_sync(0xffffffffu, r, o);
        if (tid == 0) red[0] = r;
    }
    __syncthreads();
    float var = red[0] * (1.f / CD);
    out[(size_t)row * CD + tid] = t * rsqrtf(var + 1e-5f) * gw[tid] + bw[tid];
}

// ---------------------------------------------------------------------------
// kernel_launch
// ---------------------------------------------------------------------------
extern "C" void kernel_launch(void* const* d_in, const int* in_sizes, int n_in,
                              void* d_out, int out_size) {
    const float* x   = (const float*)d_in[0];
    const int*   mask= (const int*)  d_in[1];
    const float* W1  = (const float*)d_in[2];
    const float* b1  = (const float*)d_in[3];
    const float* W2  = (const float*)d_in[4];
    const float* b2  = (const float*)d_in[5];
    const float* g1  = (const float*)d_in[6];
    const float* be1 = (const float*)d_in[7];
    const float* g2  = (const float*)d_in[8];
    const float* be2 = (const float*)d_in[9];
    float* out = (float*)d_out;

    float *pA, *pT, *pHn, *pH1, *pY;
    cudaGetSymbolAddress((void**)&pA,  g_A);
    cudaGetSymbolAddress((void**)&pT,  g_T);
    cudaGetSymbolAddress((void**)&pHn, g_Hn);
    cudaGetSymbolAddress((void**)&pH1, g_H1);
    cudaGetSymbolAddress((void**)&pY,  g_Y);

    // 1) token mean m
    k_mean<<<(CL * CDK + 255) / 256, 256>>>(x);

    // 2) quantum scores S
    k_scores<<<dim3(CL / 16, CL / 16), dim3(16, 16)>>>();

    // 3) masked row softmax -> A[b]
    k_softmax<<<CB * CL, 256>>>(mask);

    // 4) attn_out + x : T[b] = A[b] @ x[b] + x[b]
    k_sgemm<4><<<dim3(CD / 64, CL / 128, CB), 256>>>(
        pA, x, nullptr, x, pT,
        CL, CD, CL,
        (size_t)CL * CL, (size_t)CL * CD, (size_t)CL * CD, (size_t)CL * CD);

    // 5) Hn = LN(T, g1, be1)
    k_ln<<<CB * CL, CD>>>(pT, g1, be1, pHn);

    // 6) H1 = relu(Hn @ W1 + b1)   [8192x256]@[256x1024]
    k_sgemm<3><<<dim3(CF / 64, (CB * CL) / 128, 1), 256>>>(
        pHn, W1, b1, nullptr, pH1,
        CB * CL, CF, CD, 0, 0, 0, 0);

    // 7) Y = Hn + H1 @ W2 + b2     [8192x1024]@[1024x256]
    k_sgemm<5><<<dim3(CD / 64, (CB * CL) / 128, 1), 256>>>(
        pH1, W2, b2, pHn, pY,
        CB * CL, CD, CF, 0, 0, 0, 0);

    // 8) out = LN(Y, g2, be2)
    k_ln<<<CB * CL, CD>>>(pY, g2, be2, out);
}

// round 4
// speedup vs baseline: 1.8400x; 1.8400x over previous
#include <cuda_runtime.h>
#include <math.h>
#include <stdint.h>

// Problem constants (fixed by reference setup_inputs)
#define CB 4
#define CL 2048
#define CD 256
#define CH 8
#define CDK 32
#define CF 1024

// ---------------------------------------------------------------------------
// Scratch (device globals: allocation-free per harness rules)
// ---------------------------------------------------------------------------
__device__ __align__(16) float g_m[CL * CDK];                    // 256 KB
__device__ __align__(16) float g_P[(size_t)CL * CL];             // 16 MB : exp(scores)
__device__ __align__(16) float g_invden[CB * CL];                // 32 KB
__device__ __align__(16) float g_XmT[(size_t)CB * CD * CL];      // 8 MB  : masked x^T
__device__ __align__(16) float g_W1T[(size_t)CF * CD];           // 1 MB
__device__ __align__(16) float g_W2T[(size_t)CD * CF];           // 1 MB
__device__ __align__(16) float g_T[(size_t)CB * CL * CD];        // 8 MB
__device__ __align__(16) float g_Hn[(size_t)CB * CL * CD];       // 8 MB
__device__ __align__(16) float g_H1[(size_t)CB * CL * CF];       // 32 MB
__device__ __align__(16) float g_Y[(size_t)CB * CL * CD];        // 8 MB

// ---------------------------------------------------------------------------
// m[l, d] = mean over (b, h) of x[b, l, h*32 + d]
// ---------------------------------------------------------------------------
__global__ void k_mean(const float* __restrict__ x) {
    int idx = blockIdx.x * blockDim.x + threadIdx.x;
    if (idx >= CL * CDK) return;
    int l = idx / CDK;
    int d = idx % CDK;
    float s = 0.f;
#pragma unroll
    for (int b = 0; b < CB; b++)
#pragma unroll
        for (int h = 0; h < CH; h++)
            s += x[((size_t)(b * CL) + l) * CD + h * CDK + d];
    g_m[idx] = s * (1.f / 32.f);
}

// ---------------------------------------------------------------------------
// P[i, j] = exp( sin(clip(m_i . m_j, -pi, pi) * 0.5)^2 )  (unnormalized)
// ---------------------------------------------------------------------------
__global__ void k_scores() {
    __shared__ float mi[16][33];
    __shared__ float mj[16][33];
    int i0 = blockIdx.y * 16;
    int j0 = blockIdx.x * 16;
    int tx = threadIdx.x, ty = threadIdx.y;
    int t = ty * 16 + tx;
    for (int v = t; v < 16 * 32; v += 256) {
        int r = v >> 5, c = v & 31;
        mi[r][c] = g_m[(i0 + r) * CDK + c];
        mj[r][c] = g_m[(j0 + r) * CDK + c];
    }
    __syncthreads();
    float dot = 0.f;
#pragma unroll
    for (int k = 0; k < 32; k++) dot = fmaf(mi[ty][k], mj[tx][k], dot);
    const float PI = 3.14159265358979323846f;
    float ang = fminf(fmaxf(dot, -PI), PI);
    float s = sinf(ang * 0.5f);
    g_P[(size_t)(i0 + ty) * CL + (j0 + tx)] = expf(s * s);
}

// ---------------------------------------------------------------------------
// invden[b][i] = 1 / sum_j P[i,j] * (mask[b][j] != 0)
// ---------------------------------------------------------------------------
__global__ void k_denom(const int* __restrict__ mask) {
    __shared__ float red[CB][8];
    int i = blockIdx.x;
    int tid = threadIdx.x;  // 256
    const float* Prow = g_P + (size_t)i * CL;
    float acc[CB] = {0.f, 0.f, 0.f, 0.f};
    for (int j = tid; j < CL; j += 256) {
        float p = Prow[j];
#pragma unroll
        for (int b = 0; b < CB; b++)
            acc[b] += (mask[b * CL + j] != 0) ? p : 0.f;
    }
#pragma unroll
    for (int b = 0; b < CB; b++) {
        float v = acc[b];
        for (int o = 16; o > 0; o >>= 1) v += __shfl_xor_sync(0xffffffffu, v, o);
        if ((tid & 31) == 0) red[b][tid >> 5] = v;
    }
    __syncthreads();
    if (tid < CB) {
        float s = 0.f;
#pragma unroll
        for (int w = 0; w < 8; w++) s += red[tid][w];
        g_invden[tid * CL + i] = 1.f / s;
    }
}

// ---------------------------------------------------------------------------
// XmT[b][d][j] = mask[b][j] * x[b][j][d]   (masked, transposed values)
// ---------------------------------------------------------------------------
__global__ void k_xm(const float* __restrict__ x, const int* __restrict__ mask) {
    __shared__ float t[32][33];
    int b = blockIdx.z;
    int j0 = blockIdx.x * 32, d0 = blockIdx.y * 32;
    for (int i = threadIdx.y; i < 32; i += 8) {
        float v = x[((size_t)b * CL + j0 + i) * CD + d0 + threadIdx.x];
        t[i][threadIdx.x] = (mask[b * CL + j0 + i] != 0) ? v : 0.f;
    }
    __syncthreads();
    for (int i = threadIdx.y; i < 32; i += 8)
        g_XmT[((size_t)b * CD + d0 + i) * CL + j0 + threadIdx.x] = t[threadIdx.x][i];
}

// Generic transpose: out[c][r] = in[r][c], in is R x C
__global__ void k_xpose(const float* __restrict__ in, float* __restrict__ out, int R, int C) {
    __shared__ float t[32][33];
    int r0 = blockIdx.y * 32, c0 = blockIdx.x * 32;
    for (int i = threadIdx.y; i < 32; i += 8)
        t[i][threadIdx.x] = in[(size_t)(r0 + i) * C + c0 + threadIdx.x];
    __syncthreads();
    for (int i = threadIdx.y; i < 32; i += 8)
        out[(size_t)(c0 + i) * R + r0 + threadIdx.x] = t[threadIdx.x][i];
}

// ---------------------------------------------------------------------------
// TF32 mma.sync helpers
// ---------------------------------------------------------------------------
__device__ __forceinline__ uint32_t f2tf32(float x) {
    uint32_t r;
    asm("cvt.rna.tf32.f32 %0, %1;" : "=r"(r) : "f"(x));
    return r;
}
__device__ __forceinline__ void mma16n8k8(float* d, const uint4& a, const uint2& b) {
    asm volatile(
        "mma.sync.aligned.m16n8k8.row.col.f32.tf32.tf32.f32 "
        "{%0,%1,%2,%3}, {%4,%5,%6,%7}, {%8,%9}, {%0,%1,%2,%3};"
        : "+f"(d[0]), "+f"(d[1]), "+f"(d[2]), "+f"(d[3])
        : "r"(a.x), "r"(a.y), "r"(a.z), "r"(a.w), "r"(b.x), "r"(b.y));
}

// ---------------------------------------------------------------------------
// TF32 tensor-core GEMM: C[M,N] = A[M,K] @ B[N,K]^T  (both operands K-major)
// CTA tile 128x128, BK=16, 8 warps (2x4), warp tile 64x32 via m16n8k8.
// SMEM tiles stored in MMA *fragment layout* (scattered at STS time).
// OPT bits: 1 = +bias, 2 = relu, 4 = +residual, 8 = row-scale
// ---------------------------------------------------------------------------
template <int OPT>
__global__ void __launch_bounds__(256) k_mmagemm(
    const float* __restrict__ A, const float* __restrict__ B,
    const float* __restrict__ bias, const float* __restrict__ Res,
    const float* __restrict__ rscale, float* __restrict__ C,
    int M, int N, int K,
    size_t sA, size_t sB, size_t sR, size_t sS, size_t sC)
{
    __shared__ uint32_t As[2][2048];   // fragment-layout A tile (128m x 16k)
    __shared__ uint32_t Bs[2][2048];   // fragment-layout B tile (128n x 16k)

    const int tid = threadIdx.x;
    const int lane = tid & 31;
    const int wid = tid >> 5;
    const int wr = wid >> 2;       // warp row (0..1) -> 64 rows
    const int wc = wid & 3;        // warp col (0..3) -> 32 cols

    A += (size_t)blockIdx.z * sA;
    B += (size_t)blockIdx.z * sB;
    C += (size_t)blockIdx.z * sC;
    if (OPT & 4) Res += (size_t)blockIdx.z * sR;
    if (OPT & 8) rscale += (size_t)blockIdx.z * sS;

    const int m0 = blockIdx.y * 128;
    const int n0 = blockIdx.x * 128;

    // ---- loader setup: each thread owns 2 float4 of A and 2 float4 of B ----
    const float* aptr[2];
    const float* bptr[2];
    int aoff[2][4], boff[2][4];
#pragma unroll
    for (int i = 0; i < 2; i++) {
        int f = tid + i * 256;          // 0..511
        int r = f >> 2;                 // tile row 0..127
        int q = f & 3;                  // float4 index in 16-float row
        aptr[i] = A + (size_t)(m0 + r) * K + q * 4;
        bptr[i] = B + (size_t)(n0 + r) * K + q * 4;
#pragma unroll
        for (int j = 0; j < 4; j++) {
            int k = q * 4 + j;          // 0..15 within chunk
            int ks = k >> 3, kk = k & 7;
            // A fragment scatter: [ks2][wr2][mfrag4][lane32][slot4]
            int wrr = r >> 6, mf = (r & 63) >> 4, rr = r & 15;
            int La = (rr & 7) * 4 + (kk & 3);
            int sa = (rr >> 3) + 2 * (kk >> 2);
            aoff[i][j] = ((ks * 2 + wrr) * 4 + mf) * 128 + La * 4 + sa;
            // B fragment scatter: [ks2][wc4][nfrag4][lane32][slot2]
            int wcc = r >> 5, nf = (r & 31) >> 3, nn = r & 7;
            int Lb = nn * 4 + (kk & 3);
            int sb = kk >> 2;
            boff[i][j] = ((ks * 4 + wcc) * 4 + nf) * 64 + Lb * 2 + sb;
        }
    }

    float acc[4][4][4];
#pragma unroll
    for (int i = 0; i < 4; i++)
#pragma unroll
        for (int j = 0; j < 4; j++)
#pragma unroll
            for (int q = 0; q < 4; q++) acc[i][j][q] = 0.f;

    const int NC = K >> 4;
    float4 pa[2], pb[2];

    // prologue: chunk 0
#pragma unroll
    for (int i = 0; i < 2; i++) {
        pa[i] = *(const float4*)aptr[i];
        pb[i] = *(const float4*)bptr[i];
    }
#pragma unroll
    for (int i = 0; i < 2; i++) {
        As[0][aoff[i][0]] = f2tf32(pa[i].x);
        As[0][aoff[i][1]] = f2tf32(pa[i].y);
        As[0][aoff[i][2]] = f2tf32(pa[i].z);
        As[0][aoff[i][3]] = f2tf32(pa[i].w);
        Bs[0][boff[i][0]] = f2tf32(pb[i].x);
        Bs[0][boff[i][1]] = f2tf32(pb[i].y);
        Bs[0][boff[i][2]] = f2tf32(pb[i].z);
        Bs[0][boff[i][3]] = f2tf32(pb[i].w);
    }
    __syncthreads();

    for (int c = 0; c < NC; c++) {
        const int buf = c & 1;
        if (c + 1 < NC) {
            const int k0 = (c + 1) << 4;
#pragma unroll
            for (int i = 0; i < 2; i++) {
                pa[i] = *(const float4*)(aptr[i] + k0);
                pb[i] = *(const float4*)(bptr[i] + k0);
            }
        }
#pragma unroll
        for (int ks = 0; ks < 2; ks++) {
            uint4 af[4];
            uint2 bf[4];
#pragma unroll
            for (int i = 0; i < 4; i++)
                af[i] = *(const uint4*)&As[buf][((ks * 2 + wr) * 4 + i) * 128 + lane * 4];
#pragma unroll
            for (int j = 0; j < 4; j++)
                bf[j] = *(const uint2*)&Bs[buf][((ks * 4 + wc) * 4 + j) * 64 + lane * 2];
#pragma unroll
            for (int i = 0; i < 4; i++)
#pragma unroll
                for (int j = 0; j < 4; j++)
                    mma16n8k8(acc[i][j], af[i], bf[j]);
        }
        if (c + 1 < NC) {
            const int nb = buf ^ 1;
#pragma unroll
            for (int i = 0; i < 2; i++) {
                As[nb][aoff[i][0]] = f2tf32(pa[i].x);
                As[nb][aoff[i][1]] = f2tf32(pa[i].y);
                As[nb][aoff[i][2]] = f2tf32(pa[i].z);
                As[nb][aoff[i][3]] = f2tf32(pa[i].w);
                Bs[nb][boff[i][0]] = f2tf32(pb[i].x);
                Bs[nb][boff[i][1]] = f2tf32(pb[i].y);
                Bs[nb][boff[i][2]] = f2tf32(pb[i].z);
                Bs[nb][boff[i][3]] = f2tf32(pb[i].w);
            }
        }
        __syncthreads();
    }

    // ---- epilogue ----
    const int rbase = m0 + wr * 64;
    const int cbase = n0 + wc * 32;
#pragma unroll
    for (int i = 0; i < 4; i++) {
        int row_lo = rbase + i * 16 + (lane >> 2);
        int row_hi = row_lo + 8;
        float rs_lo = 1.f, rs_hi = 1.f;
        if (OPT & 8) { rs_lo = rscale[row_lo]; rs_hi = rscale[row_hi]; }
#pragma unroll
        for (int j = 0; j < 4; j++) {
            int col = cbase + j * 8 + (lane & 3) * 2;
            float2 lo = make_float2(acc[i][j][0], acc[i][j][1]);
            float2 hi = make_float2(acc[i][j][2], acc[i][j][3]);
            if (OPT & 8) {
                lo.x *= rs_lo; lo.y *= rs_lo;
                hi.x *= rs_hi; hi.y *= rs_hi;
            }
            if (OPT & 1) {
                float2 bb = *(const float2*)&bias[col];
                lo.x += bb.x; lo.y += bb.y;
                hi.x += bb.x; hi.y += bb.y;
            }
            if (OPT & 2) {
                lo.x = fmaxf(lo.x, 0.f); lo.y = fmaxf(lo.y, 0.f);
                hi.x = fmaxf(hi.x, 0.f); hi.y = fmaxf(hi.y, 0.f);
            }
            if (OPT & 4) {
                float2 r0 = *(const float2*)&Res[(size_t)row_lo * N + col];
                float2 r1 = *(const float2*)&Res[(size_t)row_hi * N + col];
                lo.x += r0.x; lo.y += r0.y;
                hi.x += r1.x; hi.y += r1.y;
            }
            *(float2*)&C[(size_t)row_lo * N + col] = lo;
            *(float2*)&C[(size_t)row_hi * N + col] = hi;
        }
    }
}

// ---------------------------------------------------------------------------
// LayerNorm over last dim D=256 (one block of 256 threads per row)
// ---------------------------------------------------------------------------
__global__ void k_ln(const float* __restrict__ in, const float* __restrict__ gw,
                     const float* __restrict__ bw, float* __restrict__ out) {
    __shared__ float red[8];
    int row = blockIdx.x;
    int tid = threadIdx.x;
    float v = in[(size_t)row * CD + tid];

    float s = v;
    for (int o = 16; o > 0; o >>= 1) s += __shfl_xor_sync(0xffffffffu, s, o);
    if ((tid & 31) == 0) red[tid >> 5] = s;
    __syncthreads();
    if (tid < 32) {
        float r = (tid < 8) ? red[tid] : 0.f;
        for (int o = 4; o > 0; o >>= 1) r += __shfl_xor_sync(0xffffffffu, r, o);
        if (tid == 0) red[0] = r;
    }
    __syncthreads();
    float mu = red[0] * (1.f / CD);
    __syncthreads();

    float t = v - mu;
    float s2 = t * t;
    for (int o = 16; o > 0; o >>= 1) s2 += __shfl_xor_sync(0xffffffffu, s2, o);
    if ((tid & 31) == 0) red[tid >> 5] = s2;
    __syncthreads();
    if (tid < 32) {
        float r = (tid < 8) ? red[tid] : 0.f;
        for (int o = 4; o > 0; o >>= 1) r += __shfl_xor_sync(0xffffffffu, r, o);
        if (tid == 0) red[0] = r;
    }
    __syncthreads();
    float var = red[0] * (1.f / CD);
    out[(size_t)row * CD + tid] = t * rsqrtf(var + 1e-5f) * gw[tid] + bw[tid];
}

// ---------------------------------------------------------------------------
// kernel_launch
// ---------------------------------------------------------------------------
extern "C" void kernel_launch(void* const* d_in, const int* in_sizes, int n_in,
                              void* d_out, int out_size) {
    const float* x    = (const float*)d_in[0];
    const int*   mask = (const int*)  d_in[1];
    const float* W1   = (const float*)d_in[2];
    const float* b1   = (const float*)d_in[3];
    const float* W2   = (const float*)d_in[4];
    const float* b2   = (const float*)d_in[5];
    const float* g1   = (const float*)d_in[6];
    const float* be1  = (const float*)d_in[7];
    const float* g2   = (const float*)d_in[8];
    const float* be2  = (const float*)d_in[9];
    float* out = (float*)d_out;

    float *pP, *pInv, *pXmT, *pW1T, *pW2T, *pT, *pHn, *pH1, *pY;
    cudaGetSymbolAddress((void**)&pP,   g_P);
    cudaGetSymbolAddress((void**)&pInv, g_invden);
    cudaGetSymbolAddress((void**)&pXmT, g_XmT);
    cudaGetSymbolAddress((void**)&pW1T, g_W1T);
    cudaGetSymbolAddress((void**)&pW2T, g_W2T);
    cudaGetSymbolAddress((void**)&pT,   g_T);
    cudaGetSymbolAddress((void**)&pHn,  g_Hn);
    cudaGetSymbolAddress((void**)&pH1,  g_H1);
    cudaGetSymbolAddress((void**)&pY,   g_Y);

    // 1) token mean
    k_mean<<<(CL * CDK + 255) / 256, 256>>>(x);
    // 2) P = exp(scores)
    k_scores<<<dim3(CL / 16, CL / 16), dim3(16, 16)>>>();
    // 3) per-batch softmax denominators
    k_denom<<<CL, 256>>>(mask);
    // 4) operand transposes
    k_xm<<<dim3(CL / 32, CD / 32, CB), dim3(32, 8)>>>(x, mask);
    k_xpose<<<dim3(CF / 32, CD / 32), dim3(32, 8)>>>(W1, pW1T, CD, CF);
    k_xpose<<<dim3(CD / 32, CF / 32), dim3(32, 8)>>>(W2, pW2T, CF, CD);

    // 5) T_b = (P @ XmT_b^T) * invden_b + x_b      [attn_out + residual]
    k_mmagemm<12><<<dim3(CD / 128, CL / 128, CB), 256>>>(
        pP, pXmT, nullptr, x, pInv, pT,
        CL, CD, CL,
        0, (size_t)CD * CL, (size_t)CL * CD, (size_t)CL, (size_t)CL * CD);

    // 6) Hn = LN(T, g1, be1)
    k_ln<<<CB * CL, CD>>>(pT, g1, be1, pHn);

    // 7) H1 = relu(Hn @ W1 + b1)    [8192x256] @ [1024x256]^T
    k_mmagemm<3><<<dim3(CF / 128, (CB * CL) / 128, 1), 256>>>(
        pHn, pW1T, b1, nullptr, nullptr, pH1,
        CB * CL, CF, CD, 0, 0, 0, 0, 0);

    // 8) Y = Hn + H1 @ W2 + b2      [8192x1024] @ [256x1024]^T
    k_mmagemm<5><<<dim3(CD / 128, (CB * CL) / 128, 1), 256>>>(
        pH1, pW2T, b2, pHn, nullptr, pY,
        CB * CL, CD, CF, 0, 0, 0, 0, 0);

    // 9) out = LN(Y, g2, be2)
    k_ln<<<CB * CL, CD>>>(pY, g2, be2, out);
}